// round 16
// baseline (speedup 1.0000x reference)
#include <cuda_runtime.h>

// FINAL — round-7 kernel. Session best, reproduced 5x (R7, R11-R15):
//   bench 82.4-83.4us (harness noise band), kernel 77.3 +/- 0.4us,
//   DRAM 78.0-78.8% of spec (~6.2 TB/s), rel_err 3.2e-6.
//   141.5us (first correct) -> 82.4us: 1.72x, sitting on the HBM roofline.
//
// Four-step 1024-point inverse FFT (reference == normalized inverse DFT):
//   1024 = 32 x 32, one warp lane per column, one warp per row.
//   A[k1,b]    = FFT32_a( x[32a+b] )          (register FFT, thread = b = lane)
//   A'[k1,b]   = A[k1,b] * (1/1024) * W1024^{b*k1}   (pure-FMA chain)
//   X[k1+32k2] = FFT32_b( A'[k1,b] )          (u64 XOR-swizzled transpose)
//
// Session-validated design facts (15 rounds of HW evidence):
//  - the reference's quantized u/l matrix split sums exactly to the IDFT
//    matrix; the whole pipeline is a normalized 1024-pt inverse DFT, so the
//    matmuls/tensor cores are unnecessary.
//  - packed f32x2 butterflies (add.rn.f32x2 / fma.rn.f32x2): u+v / u-v in 2
//    instructions; bought DRAM% while the kernel was issue-count-bound.
//  - twiddles must be pure FMA chains; any load (LDS or LDG) on the twiddle
//    path exposes latency and regresses ~25% (v5/v6).
//  - 256-thread CTAs + burst LDG/STG + CTA retire/relaunch is the best supply
//    structure; persistence, cp.async pipelines, 128-thr CTAs, .cs hints,
//    and occupancy changes in either direction all regressed or tied.
//  - ~6.2 TB/s is the memory-system ceiling for this 50/50 read/write
//    streaming mix: two independent supply structures plateau there with no
//    on-chip pipe above 45%. Traffic (512 MB) is compulsory.

#define NFFT 1024
#define WARPS_PER_CTA 8
#define NT (32 * WARPS_PER_CTA)

typedef unsigned long long u64;

__device__ __forceinline__ u64 pk2(float r, float i) {
    u64 o; asm("mov.b64 %0, {%1, %2};" : "=l"(o) : "f"(r), "f"(i)); return o;
}
__device__ __forceinline__ void unpk2(u64 a, float& r, float& i) {
    asm("mov.b64 {%0, %1}, %2;" : "=f"(r), "=f"(i) : "l"(a));
}
__device__ __forceinline__ u64 add2(u64 a, u64 b) {
    u64 o; asm("add.rn.f32x2 %0, %1, %2;" : "=l"(o) : "l"(a), "l"(b)); return o;
}
__device__ __forceinline__ u64 fma2(u64 a, u64 b, u64 c) {
    u64 o; asm("fma.rn.f32x2 %0, %1, %2, %3;" : "=l"(o) : "l"(a), "l"(b), "l"(c));
    return o;
}

__device__ __forceinline__ int brev5(int x) {
    return ((x & 1) << 4) | ((x & 2) << 2) | (x & 4) | ((x & 8) >> 2) | ((x & 16) >> 4);
}

// Butterfly, twiddle == 1:  A' = A+B, B' = A-B.          (2 packed inst)
__device__ __forceinline__ void bflyT(u64& A, u64& B, u64 NEG1) {
    const u64 s = add2(A, B);
    B = fma2(B, NEG1, A);          // A - B
    A = s;
}
// Butterfly, twiddle == +i:  B' = i*(A-B) = (-di, dr).
__device__ __forceinline__ void bflyI(u64& A, u64& B, u64 NEG1) {
    const u64 s = add2(A, B);
    const u64 d = fma2(B, NEG1, A);
    float dr, di; unpk2(d, dr, di);
    A = s;
    B = pk2(-di, dr);
}
// Butterfly, general twiddle (C,S) compile-time: scalar FFMA-imm cmul.
__device__ __forceinline__ void bflyG(u64& A, u64& B, u64 NEG1, float C, float S) {
    const u64 s = add2(A, B);
    const u64 d = fma2(B, NEG1, A);
    float dr, di; unpk2(d, dr, di);
    A = s;
    B = pk2(dr * C - di * S, dr * S + di * C);
}

// In-place radix-2 DIF FFT-32, inverse sign (W = e^{+2*pi*i/32}), packed.
// Input natural order; output bit-reversed: z[p] holds X[brev5(p)].
__device__ __forceinline__ void fft32_dif_pk(u64* z, u64 NEG1) {
    const float TC[16] = {
        1.0f,           0.98078528040f,  0.92387953251f,  0.83146961230f,
        0.70710678119f, 0.55557023302f,  0.38268343236f,  0.19509032202f,
        0.0f,          -0.19509032202f, -0.38268343236f, -0.55557023302f,
       -0.70710678119f,-0.83146961230f, -0.92387953251f, -0.98078528040f };
    const float TS[16] = {
        0.0f,           0.19509032202f,  0.38268343236f,  0.55557023302f,
        0.70710678119f, 0.83146961230f,  0.92387953251f,  0.98078528040f,
        1.0f,           0.98078528040f,  0.92387953251f,  0.83146961230f,
        0.70710678119f, 0.55557023302f,  0.38268343236f,  0.19509032202f };

    #pragma unroll
    for (int s = 0; s < 5; s++) {
        const int L = 32 >> s;
        const int half = L >> 1;
        #pragma unroll
        for (int s0 = 0; s0 < 32; s0 += L) {
            #pragma unroll
            for (int j = 0; j < half; j++) {
                const int i0 = s0 + j;
                const int i1 = i0 + half;
                const int tw = j << s;                 // compile-time, < 16
                if (tw == 0)       bflyT(z[i0], z[i1], NEG1);
                else if (tw == 8)  bflyI(z[i0], z[i1], NEG1);
                else               bflyG(z[i0], z[i1], NEG1, TC[tw], TS[tw]);
            }
        }
    }
}

__device__ __forceinline__ float2 cmulf(float2 a, float2 b) {
    return make_float2(a.x * b.x - a.y * b.y, a.x * b.y + a.y * b.x);
}

__global__ void __launch_bounds__(NT, 3)
ifft1024_v7(const float* __restrict__ re,
            const float* __restrict__ im,
            float* __restrict__ out,
            int batch)
{
    // Packed u64 32x32 transpose buffer per warp; XOR swizzle (col = b ^ k1)
    // is conflict-free in both directions for 8-byte accesses.
    __shared__ u64 tbuf[WARPS_PER_CTA][1024];

    const int lane = threadIdx.x & 31;
    const int w    = threadIdx.x >> 5;
    const size_t row = (size_t)blockIdx.x * WARPS_PER_CTA + w;

    const float* __restrict__ rr = re + row * NFFT;
    const float* __restrict__ ri = im + row * NFFT;

    // Load x[32a + lane] (coalesced 128B per warp instruction) and pack.
    u64 z[32];
    #pragma unroll
    for (int a = 0; a < 32; a++) {
        z[a] = pk2(rr[32 * a + lane], ri[32 * a + lane]);
    }

    const u64 NEG1 = pk2(-1.0f, -1.0f);

    // Twiddle bases (data-independent: overlaps LDG latency).
    float2 w1;
    __sincosf(6.135923151542565e-3f * (float)lane, &w1.y, &w1.x);  // W1024^lane
    const float2 wb2  = cmulf(w1, w1);
    const float2 wb4  = cmulf(wb2, wb2);
    const float2 w8   = cmulf(wb4, wb4);    // W^{8b}
    const float2 w16  = cmulf(w8, w8);      // W^{16b}
    const float2 w24  = cmulf(w16, w8);     // W^{24b}

    // FFT over a.  z[p] = A[brev5(p), lane].
    fft32_dif_pk(z, NEG1);

    // Apply s*W1024^{b*k1} (scale folded) and write the swizzled transpose.
    // 4-way generation, chain depth 8 (pure FMA).
    u64* sb = tbuf[w];
    {
        float2 ch = make_float2(1.0f / 1024.0f, 0.0f);   // s * W^{l*b}
        #pragma unroll
        for (int l = 0; l < 8; l++) {
            const float2 t0 = ch;
            const float2 t1 = cmulf(ch, w8);
            const float2 t2 = cmulf(ch, w16);
            const float2 t3 = cmulf(ch, w24);
            const int k[4]  = { l, l + 8, l + 16, l + 24 };
            const float2 tt[4] = { t0, t1, t2, t3 };
            #pragma unroll
            for (int q = 0; q < 4; q++) {
                const int k1 = k[q];
                const int p  = brev5(k1);
                float ar, ai; unpk2(z[p], ar, ai);
                const float2 t = tt[q];
                sb[(k1 << 5) + (lane ^ k1)] =
                    pk2(ar * t.x - ai * t.y, ar * t.y + ai * t.x);
            }
            ch = cmulf(ch, w1);
        }
    }
    __syncwarp();

    // Read row k1 = lane of the transpose (conflict-free).
    #pragma unroll
    for (int b = 0; b < 32; b++) {
        z[b] = sb[(lane << 5) + (b ^ lane)];
    }

    // FFT over b.  z[p] = X[lane + 32*brev5(p)]  (already scaled).
    fft32_dif_pk(z, NEG1);

    // Coalesced stores (128B per warp instruction).
    float* __restrict__ outr = out + row * NFFT;
    float* __restrict__ outi = out + (size_t)batch * NFFT + row * NFFT;
    #pragma unroll
    for (int p = 0; p < 32; p++) {
        const int k2 = brev5(p);
        float xr, xi; unpk2(z[p], xr, xi);
        outr[lane + 32 * k2] = xr;
        outi[lane + 32 * k2] = xi;
    }
}

extern "C" void kernel_launch(void* const* d_in, const int* in_sizes, int n_in,
                              void* d_out, int out_size)
{
    // metadata order: re, im, wr_u, wr_l, wi_u, wi_l (matrices unused: the
    // u/l split sums exactly to the IDFT matrix; the reference pipeline is a
    // normalized 1024-point inverse DFT, computed here directly).
    const float* re = (const float*)d_in[0];
    const float* im = (const float*)d_in[1];
    float* out = (float*)d_out;

    const int batch = in_sizes[0] / NFFT;            // 32768
    ifft1024_v7<<<batch / WARPS_PER_CTA, NT>>>(re, im, out, batch);
}

// round 17
// speedup vs baseline: 1.0128x; 1.0128x over previous
#include <cuda_runtime.h>

// v17 = v7 (session best, reproduced 6x: kernel 76.9-77.8us, DRAM 78.0-78.8%)
// with ONE isolated, zero-cost variable: the final global stores are emitted
// in sequential k2 order (consecutive STG instructions write consecutive
// 128B lines of the output row) instead of bit-reversed register order.
// Pure compile-time permutation: identical instruction count, identical
// per-instruction coalescing, identical registers. Tests whether write-stream
// address ordering into L2/DRAM moves the ~78% plateau.
//
// Everything else byte-identical to v7:
//   Four-step 1024-pt inverse FFT (reference == normalized inverse DFT),
//   1024 = 32x32, one warp lane per column, one warp per row.
//   packed f32x2 FFT-32 / pure-FMA mid-twiddle (scale folded) /
//   u64 XOR-swizzled transpose / FFT-32. 256-thread CTAs, burst LDG/STG.

#define NFFT 1024
#define WARPS_PER_CTA 8
#define NT (32 * WARPS_PER_CTA)

typedef unsigned long long u64;

__device__ __forceinline__ u64 pk2(float r, float i) {
    u64 o; asm("mov.b64 %0, {%1, %2};" : "=l"(o) : "f"(r), "f"(i)); return o;
}
__device__ __forceinline__ void unpk2(u64 a, float& r, float& i) {
    asm("mov.b64 {%0, %1}, %2;" : "=f"(r), "=f"(i) : "l"(a));
}
__device__ __forceinline__ u64 add2(u64 a, u64 b) {
    u64 o; asm("add.rn.f32x2 %0, %1, %2;" : "=l"(o) : "l"(a), "l"(b)); return o;
}
__device__ __forceinline__ u64 fma2(u64 a, u64 b, u64 c) {
    u64 o; asm("fma.rn.f32x2 %0, %1, %2, %3;" : "=l"(o) : "l"(a), "l"(b), "l"(c));
    return o;
}

__device__ __forceinline__ int brev5(int x) {
    return ((x & 1) << 4) | ((x & 2) << 2) | (x & 4) | ((x & 8) >> 2) | ((x & 16) >> 4);
}

// Butterfly, twiddle == 1:  A' = A+B, B' = A-B.          (2 packed inst)
__device__ __forceinline__ void bflyT(u64& A, u64& B, u64 NEG1) {
    const u64 s = add2(A, B);
    B = fma2(B, NEG1, A);          // A - B
    A = s;
}
// Butterfly, twiddle == +i:  B' = i*(A-B) = (-di, dr).
__device__ __forceinline__ void bflyI(u64& A, u64& B, u64 NEG1) {
    const u64 s = add2(A, B);
    const u64 d = fma2(B, NEG1, A);
    float dr, di; unpk2(d, dr, di);
    A = s;
    B = pk2(-di, dr);
}
// Butterfly, general twiddle (C,S) compile-time: scalar FFMA-imm cmul.
__device__ __forceinline__ void bflyG(u64& A, u64& B, u64 NEG1, float C, float S) {
    const u64 s = add2(A, B);
    const u64 d = fma2(B, NEG1, A);
    float dr, di; unpk2(d, dr, di);
    A = s;
    B = pk2(dr * C - di * S, dr * S + di * C);
}

// In-place radix-2 DIF FFT-32, inverse sign (W = e^{+2*pi*i/32}), packed.
// Input natural order; output bit-reversed: z[p] holds X[brev5(p)].
__device__ __forceinline__ void fft32_dif_pk(u64* z, u64 NEG1) {
    const float TC[16] = {
        1.0f,           0.98078528040f,  0.92387953251f,  0.83146961230f,
        0.70710678119f, 0.55557023302f,  0.38268343236f,  0.19509032202f,
        0.0f,          -0.19509032202f, -0.38268343236f, -0.55557023302f,
       -0.70710678119f,-0.83146961230f, -0.92387953251f, -0.98078528040f };
    const float TS[16] = {
        0.0f,           0.19509032202f,  0.38268343236f,  0.55557023302f,
        0.70710678119f, 0.83146961230f,  0.92387953251f,  0.98078528040f,
        1.0f,           0.98078528040f,  0.92387953251f,  0.83146961230f,
        0.70710678119f, 0.55557023302f,  0.38268343236f,  0.19509032202f };

    #pragma unroll
    for (int s = 0; s < 5; s++) {
        const int L = 32 >> s;
        const int half = L >> 1;
        #pragma unroll
        for (int s0 = 0; s0 < 32; s0 += L) {
            #pragma unroll
            for (int j = 0; j < half; j++) {
                const int i0 = s0 + j;
                const int i1 = i0 + half;
                const int tw = j << s;                 // compile-time, < 16
                if (tw == 0)       bflyT(z[i0], z[i1], NEG1);
                else if (tw == 8)  bflyI(z[i0], z[i1], NEG1);
                else               bflyG(z[i0], z[i1], NEG1, TC[tw], TS[tw]);
            }
        }
    }
}

__device__ __forceinline__ float2 cmulf(float2 a, float2 b) {
    return make_float2(a.x * b.x - a.y * b.y, a.x * b.y + a.y * b.x);
}

__global__ void __launch_bounds__(NT, 3)
ifft1024_v17(const float* __restrict__ re,
             const float* __restrict__ im,
             float* __restrict__ out,
             int batch)
{
    // Packed u64 32x32 transpose buffer per warp; XOR swizzle (col = b ^ k1)
    // is conflict-free in both directions for 8-byte accesses.
    __shared__ u64 tbuf[WARPS_PER_CTA][1024];

    const int lane = threadIdx.x & 31;
    const int w    = threadIdx.x >> 5;
    const size_t row = (size_t)blockIdx.x * WARPS_PER_CTA + w;

    const float* __restrict__ rr = re + row * NFFT;
    const float* __restrict__ ri = im + row * NFFT;

    // Load x[32a + lane] (coalesced 128B per warp instruction) and pack.
    u64 z[32];
    #pragma unroll
    for (int a = 0; a < 32; a++) {
        z[a] = pk2(rr[32 * a + lane], ri[32 * a + lane]);
    }

    const u64 NEG1 = pk2(-1.0f, -1.0f);

    // Twiddle bases (data-independent: overlaps LDG latency).
    float2 w1;
    __sincosf(6.135923151542565e-3f * (float)lane, &w1.y, &w1.x);  // W1024^lane
    const float2 wb2  = cmulf(w1, w1);
    const float2 wb4  = cmulf(wb2, wb2);
    const float2 w8   = cmulf(wb4, wb4);    // W^{8b}
    const float2 w16  = cmulf(w8, w8);      // W^{16b}
    const float2 w24  = cmulf(w16, w8);     // W^{24b}

    // FFT over a.  z[p] = A[brev5(p), lane].
    fft32_dif_pk(z, NEG1);

    // Apply s*W1024^{b*k1} (scale folded) and write the swizzled transpose.
    // 4-way generation, chain depth 8 (pure FMA).
    u64* sb = tbuf[w];
    {
        float2 ch = make_float2(1.0f / 1024.0f, 0.0f);   // s * W^{l*b}
        #pragma unroll
        for (int l = 0; l < 8; l++) {
            const float2 t0 = ch;
            const float2 t1 = cmulf(ch, w8);
            const float2 t2 = cmulf(ch, w16);
            const float2 t3 = cmulf(ch, w24);
            const int k[4]  = { l, l + 8, l + 16, l + 24 };
            const float2 tt[4] = { t0, t1, t2, t3 };
            #pragma unroll
            for (int q = 0; q < 4; q++) {
                const int k1 = k[q];
                const int p  = brev5(k1);
                float ar, ai; unpk2(z[p], ar, ai);
                const float2 t = tt[q];
                sb[(k1 << 5) + (lane ^ k1)] =
                    pk2(ar * t.x - ai * t.y, ar * t.y + ai * t.x);
            }
            ch = cmulf(ch, w1);
        }
    }
    __syncwarp();

    // Read row k1 = lane of the transpose (conflict-free).
    #pragma unroll
    for (int b = 0; b < 32; b++) {
        z[b] = sb[(lane << 5) + (b ^ lane)];
    }

    // FFT over b.  z[p] = X[lane + 32*brev5(p)]  (already scaled).
    fft32_dif_pk(z, NEG1);

    // Coalesced stores, emitted in SEQUENTIAL k2 order: consecutive STG
    // instructions write consecutive 128B lines (v7 emitted them in
    // bit-reversed address order). Compile-time permutation, same SASS count.
    float* __restrict__ outr = out + row * NFFT;
    float* __restrict__ outi = out + (size_t)batch * NFFT + row * NFFT;
    #pragma unroll
    for (int k2 = 0; k2 < 32; k2++) {
        const int p = brev5(k2);               // compile-time under unroll
        float xr, xi; unpk2(z[p], xr, xi);
        outr[lane + 32 * k2] = xr;
        outi[lane + 32 * k2] = xi;
    }
}

extern "C" void kernel_launch(void* const* d_in, const int* in_sizes, int n_in,
                              void* d_out, int out_size)
{
    // metadata order: re, im, wr_u, wr_l, wi_u, wi_l (matrices unused: the
    // u/l split sums exactly to the IDFT matrix; the reference pipeline is a
    // normalized 1024-point inverse DFT, computed here directly).
    const float* re = (const float*)d_in[0];
    const float* im = (const float*)d_in[1];
    float* out = (float*)d_out;

    const int batch = in_sizes[0] / NFFT;            // 32768
    ifft1024_v17<<<batch / WARPS_PER_CTA, NT>>>(re, im, out, batch);
}